// round 13
// baseline (speedup 1.0000x reference)
#include <cuda_runtime.h>
#include <cuda_bf16.h>
#include <cstdint>

// Problem constants
#define BATCH 64
#define OUTF  8192
#define INF   8192
#define RANK  16
#define GROUP 16
#define KC    64
#define SPLITK 4
#define NCHUNK_Q (INF / KC / SPLITK)   // 32 chunks per CTA
#define OUT_TILE 128
#define NOTILES (OUTF / OUT_TILE)      // 64
#define NBLOCKS (SPLITK * NOTILES)     // 256

#define WS_STRIDE 68               // W_s row stride: conflict-free A reads + STS.128
#define XS_STRIDE 72               // x_s row stride: conflict-free LDS.128 B reads
#define WS_FLOATS (OUT_TILE * WS_STRIDE)   // 8704 floats per stage
#define XS_FLOATS (KC * XS_STRIDE)         // 4608 floats per stage
#define MAIN_SMEM ((2 * WS_FLOATS + 2 * XS_FLOATS) * 4)   // 106496 B dynamic

// scratch: lora t partials (4 x 64x16), fragment-permuted tf32 x^T (2MB), split-K partials (8MB)
__device__ float g_tp[SPLITK][BATCH * RANK];
__device__ __align__(16) float g_xt[INF * BATCH];   // [k][p], p = fragment-permuted batch
__device__ __align__(16) float g_p[SPLITK * BATCH * OUTF];

__device__ __forceinline__ unsigned tf32_rna(float x) {
    unsigned r;
    asm("cvt.rna.tf32.f32 %0, %1;" : "=r"(r) : "f"(x));
    return r;
}
__device__ __forceinline__ float tf32f(float x) {
    return __uint_as_float(tf32_rna(x));
}

// nvfp4 (e2m1) nibble -> fp32, times scale. n in [0,16).
__device__ __forceinline__ float dec4(unsigned n, float scr) {
    unsigned m = n & 7u;
    unsigned man = (m & ((m >> 1) | (m >> 2))) & 1u;
    unsigned bits = ((126u + (m >> 1)) << 23) | (man << 22);
    if (m == 0u) bits = 0u;
    bits |= (n & 8u) << 28;
    return __uint_as_float(bits) * scr;
}

__device__ __forceinline__ void mma_tf32_16x8x8(
    float& c0, float& c1, float& c2, float& c3,
    unsigned a0, unsigned a1, unsigned a2, unsigned a3,
    unsigned b0, unsigned b1)
{
    asm volatile(
        "mma.sync.aligned.m16n8k8.row.col.f32.tf32.tf32.f32 "
        "{%0,%1,%2,%3}, {%4,%5,%6,%7}, {%8,%9}, {%0,%1,%2,%3};"
        : "+f"(c0), "+f"(c1), "+f"(c2), "+f"(c3)
        : "r"(a0), "r"(a1), "r"(a2), "r"(a3), "r"(b0), "r"(b1));
}

// decode 8 code-ints (16 weights, exactly one scale group) into 4 float4 STS
__device__ __forceinline__ void decode_half(uint4 u0, uint4 u1, float s, float* dst)
{
    unsigned codes[8] = { u0.x, u0.y, u0.z, u0.w, u1.x, u1.y, u1.z, u1.w };
    float wv[16];
    #pragma unroll
    for (int j = 0; j < 8; j++) {
        const unsigned cb = codes[j] & 0xFFu;
        wv[2 * j]     = dec4(cb & 15u, s);   // mma.tf32 truncates low mantissa bits
        wv[2 * j + 1] = dec4(cb >> 4, s);
    }
    #pragma unroll
    for (int q = 0; q < 4; q++)
        *reinterpret_cast<float4*>(dst + q * 4) =
            make_float4(wv[q * 4], wv[q * 4 + 1], wv[q * 4 + 2], wv[q * 4 + 3]);
}

// ---------------------------------------------------------------------------
// Prep kernel (512 threads):
//  blocks [0,256):    g_tp[kq][b][r] = sum over k-quarter of x[b][k]*A[r][k]
//  blocks [256,384):  g_xt[k][p] = tf32(x[perm(p)][k]) for one 64-k slab,
//    permuted col p = 32h + 4g + j holds batch 32h + 8j + g
// ---------------------------------------------------------------------------
__global__ __launch_bounds__(512) void prep_kernel(
    const float* __restrict__ x, const float* __restrict__ A)
{
    __shared__ float ts[64][65];
    const int tid = threadIdx.x;

    if (blockIdx.x < 256) {
        // ---- lora partial: block = (b, kq) ----
        const int b  = blockIdx.x >> 2;
        const int kq = blockIdx.x & 3;
        const int r = tid & 15;
        const int part = tid >> 4;          // 0..31, 64 elems each

        const float* xr = x + (size_t)b * INF + kq * (INF / 4) + part * 64;
        const float* ar = A + (size_t)r * INF + kq * (INF / 4) + part * 64;

        float s0 = 0.f, s1 = 0.f, s2 = 0.f, s3 = 0.f;
        #pragma unroll
        for (int j = 0; j < 64; j += 16) {
            #pragma unroll
            for (int u = 0; u < 4; u++) {
                float4 xv = *reinterpret_cast<const float4*>(xr + j + 4 * u);
                float4 av = *reinterpret_cast<const float4*>(ar + j + 4 * u);
                float d = xv.x * av.x + xv.y * av.y + xv.z * av.z + xv.w * av.w;
                if (u == 0) s0 += d; else if (u == 1) s1 += d;
                else if (u == 2) s2 += d; else s3 += d;
            }
        }
        float* red = &ts[0][0];
        red[tid] = (s0 + s1) + (s2 + s3);
        __syncthreads();
        if (tid < 16) {
            float t = 0.0f;
            #pragma unroll
            for (int p = 0; p < 32; p++) t += red[p * 16 + tid];
            g_tp[kq][b * RANK + tid] = t;
        }
    } else {
        // ---- x transpose slab ----
        const int slab = blockIdx.x - 256;
        const int k0 = slab * 64;
        const int b = tid >> 3;             // 0..63
        const int q = tid & 7;              // 0..7 -> float4 cols 2q, 2q+1
        const float4* x4 = reinterpret_cast<const float4*>(x);

        #pragma unroll
        for (int p = 0; p < 2; p++) {
            const int fp = 2 * q + p;
            float4 v = x4[(size_t)b * (INF / 4) + (k0 >> 2) + fp];
            const int kk = fp * 4;
            ts[kk + 0][b] = v.x;
            ts[kk + 1][b] = v.y;
            ts[kk + 2][b] = v.z;
            ts[kk + 3][b] = v.w;
        }
        __syncthreads();

        float4* out4 = reinterpret_cast<float4*>(g_xt) + (size_t)slab * 1024;
        #pragma unroll
        for (int p = 0; p < 2; p++) {
            const int f = tid + 512 * p;
            const int k = f >> 4;
            const int col4 = f & 15;
            const int h = (col4 >> 3) * 32;
            const int g = col4 & 7;
            out4[f] = make_float4(tf32f(ts[k][h + 0 + g]),
                                  tf32f(ts[k][h + 8 + g]),
                                  tf32f(ts[k][h + 16 + g]),
                                  tf32f(ts[k][h + 24 + g]));
        }
    }
}

// ---------------------------------------------------------------------------
// Main kernel: split-K=4, OUT_TILE=128, warp tile m32xn32,
// double-buffered W_s and x_s, ONE sync per chunk.
//  grid = 256: blockIdx = otile | (kq << 6). 256 threads (8 warps = 4m x 2n).
// ---------------------------------------------------------------------------
__global__ __launch_bounds__(256, 2) void qlora_main_kernel(
    const int* __restrict__ pw,        // one packed BYTE per int32 element
    const float* __restrict__ sc,
    const float* __restrict__ lB)
{
    extern __shared__ float dsm[];
    float* Wbase = dsm;                        // 2 stages of WS_FLOATS
    float* Xbase = dsm + 2 * WS_FLOATS;        // 2 stages of XS_FLOATS

    const int tid   = threadIdx.x;
    const int lane  = tid & 31;
    const int warp  = tid >> 5;
    const int otile = blockIdx.x & (NOTILES - 1);
    const int kq    = blockIdx.x >> 6;
    const int o0    = otile * OUT_TILE;

    // ---- W staging roles: thread -> (row = tid&127, k-half wh = tid>>7) ----
    const int wrow = tid & 127;
    const int wh   = tid >> 7;                  // 0,1: local k [0,32) / [32,64)
    const int* pw_row = pw + (size_t)(o0 + wrow) * (INF / 2)
                           + kq * (INF / 2 / SPLITK) + wh * 16;
    const float* sc_row = sc + (size_t)(o0 + wrow) * (INF / GROUP)
                             + kq * (INF / GROUP / SPLITK) + wh * 2;
    float* wdst_base = Wbase + wrow * WS_STRIDE + wh * 32;

    const float4* xt4 = reinterpret_cast<const float4*>(g_xt)
                      + (size_t)kq * NCHUNK_Q * 1024;

    // warp tiling: 4 m-warps x 2 n-warps; warp tile m32 x n32
    const int m0  = (warp & 3) * 32;
    const int nb  = (warp >> 2) * 32;
    const int gid = lane >> 2;
    const int tig = lane & 3;
    const int boff = nb + 4 * gid;             // permuted B column base

    // A row offsets (floats) into W_s
    const int ra0 = (m0 + gid) * WS_STRIDE;
    const int ra1 = ra0 + 8 * WS_STRIDE;
    const int ra2 = ra0 + 16 * WS_STRIDE;
    const int ra3 = ra0 + 24 * WS_STRIDE;

    float acc[2][4][4];
    #pragma unroll
    for (int mt = 0; mt < 2; mt++)
        #pragma unroll
        for (int j = 0; j < 4; j++)
            #pragma unroll
            for (int e = 0; e < 4; e++) acc[mt][j][e] = 0.0f;

    // ---- prologue: stage chunk 0; prefetch chunk 1 into regs ----
    uint4 pa = *reinterpret_cast<const uint4*>(pw_row);
    uint4 pb = *reinterpret_cast<const uint4*>(pw_row + 4);
    uint4 pc = *reinterpret_cast<const uint4*>(pw_row + 8);
    uint4 pd = *reinterpret_cast<const uint4*>(pw_row + 12);
    float s0 = sc_row[0], s1 = sc_row[1];
    float4 xr[4];
    #pragma unroll
    for (int p = 0; p < 4; p++) xr[p] = xt4[tid + 256 * p];

    decode_half(pa, pb, s0, wdst_base);
    decode_half(pc, pd, s1, wdst_base + 16);
    #pragma unroll
    for (int p = 0; p < 4; p++) {
        const int f = tid + 256 * p;
        const int k = f >> 4;
        const int c4 = (f & 15) * 4;
        *reinterpret_cast<float4*>(&Xbase[k * XS_STRIDE + c4]) = xr[p];
    }
    // prefetch chunk 1
    pa = *reinterpret_cast<const uint4*>(pw_row + 32);
    pb = *reinterpret_cast<const uint4*>(pw_row + 36);
    pc = *reinterpret_cast<const uint4*>(pw_row + 40);
    pd = *reinterpret_cast<const uint4*>(pw_row + 44);
    s0 = sc_row[4]; s1 = sc_row[5];
    #pragma unroll
    for (int p = 0; p < 4; p++) xr[p] = xt4[1024 + tid + 256 * p];
    __syncthreads();

    for (int c = 0; c < NCHUNK_Q; c++) {
        // ---- MMA phase on stage c&1 ----
        const float* Wbuf = Wbase + (c & 1) * WS_FLOATS;
        const float* Xbuf = Xbase + (c & 1) * XS_FLOATS;
        #pragma unroll
        for (int s = 0; s < 8; s++) {
            const int kl = s * 8;
            const int k0i = kl + tig;
            unsigned a00 = __float_as_uint(Wbuf[ra0 + k0i]);
            unsigned a01 = __float_as_uint(Wbuf[ra1 + k0i]);
            unsigned a02 = __float_as_uint(Wbuf[ra0 + k0i + 4]);
            unsigned a03 = __float_as_uint(Wbuf[ra1 + k0i + 4]);
            unsigned a10 = __float_as_uint(Wbuf[ra2 + k0i]);
            unsigned a11 = __float_as_uint(Wbuf[ra3 + k0i]);
            unsigned a12 = __float_as_uint(Wbuf[ra2 + k0i + 4]);
            unsigned a13 = __float_as_uint(Wbuf[ra3 + k0i + 4]);
            const float* bp = Xbuf + k0i * XS_STRIDE + boff;
            float4 b0v = *reinterpret_cast<const float4*>(bp);
            float4 b1v = *reinterpret_cast<const float4*>(bp + 4 * XS_STRIDE);

            mma_tf32_16x8x8(acc[0][0][0], acc[0][0][1], acc[0][0][2], acc[0][0][3],
                            a00, a01, a02, a03, __float_as_uint(b0v.x), __float_as_uint(b1v.x));
            mma_tf32_16x8x8(acc[0][1][0], acc[0][1][1], acc[0][1][2], acc[0][1][3],
                            a00, a01, a02, a03, __float_as_uint(b0v.y), __float_as_uint(b1v.y));
            mma_tf32_16x8x8(acc[0][2][0], acc[0][2][1], acc[0][2][2], acc[0][2][3],
                            a00, a01, a02, a03, __float_as_uint(b0v.z), __float_as_uint(b1v.z));
            mma_tf32_16x8x8(acc[0][3][0], acc[0][3][1], acc[0][3][2], acc[0][3][3],
                            a00, a01, a02, a03, __float_as_uint(b0v.w), __float_as_uint(b1v.w));
            mma_tf32_16x8x8(acc[1][0][0], acc[1][0][1], acc[1][0][2], acc[1][0][3],
                            a10, a11, a12, a13, __float_as_uint(b0v.x), __float_as_uint(b1v.x));
            mma_tf32_16x8x8(acc[1][1][0], acc[1][1][1], acc[1][1][2], acc[1][1][3],
                            a10, a11, a12, a13, __float_as_uint(b0v.y), __float_as_uint(b1v.y));
            mma_tf32_16x8x8(acc[1][2][0], acc[1][2][1], acc[1][2][2], acc[1][2][3],
                            a10, a11, a12, a13, __float_as_uint(b0v.z), __float_as_uint(b1v.z));
            mma_tf32_16x8x8(acc[1][3][0], acc[1][3][1], acc[1][3][2], acc[1][3][3],
                            a10, a11, a12, a13, __float_as_uint(b0v.w), __float_as_uint(b1v.w));
        }

        // ---- stage chunk c+1 into the other buffers (overlaps MMA drain) ----
        if (c + 1 < NCHUNK_Q) {
            const int st = (c + 1) & 1;
            float* wdst = wdst_base + st * WS_FLOATS;
            decode_half(pa, pb, s0, wdst);
            decode_half(pc, pd, s1, wdst + 16);
            float* xdst = Xbase + st * XS_FLOATS;
            #pragma unroll
            for (int p = 0; p < 4; p++) {
                const int f = tid + 256 * p;
                const int k = f >> 4;
                const int c4 = (f & 15) * 4;
                *reinterpret_cast<float4*>(&xdst[k * XS_STRIDE + c4]) = xr[p];
            }

            // ---- prefetch chunk c+2 into regs ----
            if (c + 2 < NCHUNK_Q) {
                const int* pn = pw_row + (c + 2) * 32;
                pa = *reinterpret_cast<const uint4*>(pn);
                pb = *reinterpret_cast<const uint4*>(pn + 4);
                pc = *reinterpret_cast<const uint4*>(pn + 8);
                pd = *reinterpret_cast<const uint4*>(pn + 12);
                s0 = sc_row[(c + 2) * 4];
                s1 = sc_row[(c + 2) * 4 + 1];
                const float4* src = xt4 + (size_t)(c + 2) * 1024;
                #pragma unroll
                for (int p = 0; p < 4; p++) xr[p] = src[tid + 256 * p];
            }
        }
        __syncthreads();
    }

    // ---- epilogue (reuse dsm for lb/t) ----
    float* pout = g_p + (size_t)kq * BATCH * OUTF;

    if (kq == 0) {
        float* lb_s = dsm;                     // 2048 floats
        float* t_s  = dsm + 2048;              // 1024 floats
        for (int i = tid; i < OUT_TILE * RANK; i += 256)
            lb_s[i] = lB[(size_t)o0 * RANK + i];
        for (int i = tid; i < BATCH * RANK; i += 256)
            t_s[i] = ((g_tp[0][i] + g_tp[1][i]) + (g_tp[2][i] + g_tp[3][i]));
        __syncthreads();

        #pragma unroll
        for (int mt = 0; mt < 2; mt++) {
            float lbr0[RANK], lbr1[RANK];
            #pragma unroll
            for (int r = 0; r < RANK; r++) {
                lbr0[r] = lb_s[(m0 + 16 * mt + gid) * RANK + r];
                lbr1[r] = lb_s[(m0 + 16 * mt + gid + 8) * RANK + r];
            }
            #pragma unroll
            for (int j = 0; j < 4; j++) {
                const int bc0 = nb + 8 * j + 2 * tig;
                const int bc1 = bc0 + 1;
                float d00 = 0.f, d01 = 0.f, d10 = 0.f, d11 = 0.f;
                #pragma unroll
                for (int r = 0; r < RANK; r++) {
                    const float t0 = t_s[bc0 * RANK + r];
                    const float t1 = t_s[bc1 * RANK + r];
                    d00 += t0 * lbr0[r];
                    d01 += t1 * lbr0[r];
                    d10 += t0 * lbr1[r];
                    d11 += t1 * lbr1[r];
                }
                const int og0 = o0 + m0 + 16 * mt + gid;
                pout[(size_t)bc0 * OUTF + og0]     = acc[mt][j][0] + d00;
                pout[(size_t)bc1 * OUTF + og0]     = acc[mt][j][1] + d01;
                pout[(size_t)bc0 * OUTF + og0 + 8] = acc[mt][j][2] + d10;
                pout[(size_t)bc1 * OUTF + og0 + 8] = acc[mt][j][3] + d11;
            }
        }
    } else {
        #pragma unroll
        for (int mt = 0; mt < 2; mt++)
            #pragma unroll
            for (int j = 0; j < 4; j++) {
                const int bc0 = nb + 8 * j + 2 * tig;
                const int bc1 = bc0 + 1;
                const int og0 = o0 + m0 + 16 * mt + gid;
                pout[(size_t)bc0 * OUTF + og0]     = acc[mt][j][0];
                pout[(size_t)bc1 * OUTF + og0]     = acc[mt][j][1];
                pout[(size_t)bc0 * OUTF + og0 + 8] = acc[mt][j][2];
                pout[(size_t)bc1 * OUTF + og0 + 8] = acc[mt][j][3];
            }
    }
}

// ---------------------------------------------------------------------------
// Reduce kernel: out = p0 + p1 + p2 + p3 (elementwise, float4)
// ---------------------------------------------------------------------------
__global__ __launch_bounds__(256) void reduce_kernel(float* __restrict__ out)
{
    const int i = blockIdx.x * 256 + threadIdx.x;      // float4 index
    const float4* p0 = reinterpret_cast<const float4*>(g_p);
    const int q = (BATCH * OUTF) / 4;
    float4 a = p0[i];
    float4 b = p0[i + q];
    float4 c = p0[i + 2 * q];
    float4 d = p0[i + 3 * q];
    reinterpret_cast<float4*>(out)[i] =
        make_float4((a.x + b.x) + (c.x + d.x), (a.y + b.y) + (c.y + d.y),
                    (a.z + b.z) + (c.z + d.z), (a.w + b.w) + (c.w + d.w));
}

// ---------------------------------------------------------------------------
// launch
// inputs: x f32(64,8192), packed_weight int32(8192,4096) [byte per element],
//   weight_block_scales f32(8192,512), lora_A f32(16,8192), lora_B f32(8192,16)
// output: f32 (64,8192)
// ---------------------------------------------------------------------------
extern "C" void kernel_launch(void* const* d_in, const int* in_sizes, int n_in,
                              void* d_out, int out_size)
{
    const float* x   = (const float*)d_in[0];
    const int*   pw  = (const int*)d_in[1];
    const float* sc  = (const float*)d_in[2];
    const float* lA  = (const float*)d_in[3];
    const float* lB  = (const float*)d_in[4];
    float*       out = (float*)d_out;

    cudaFuncSetAttribute(qlora_main_kernel,
                         cudaFuncAttributeMaxDynamicSharedMemorySize, MAIN_SMEM);

    prep_kernel<<<256 + 128, 512>>>(x, lA);
    qlora_main_kernel<<<NBLOCKS, 256, MAIN_SMEM>>>(pw, sc, lB);
    reduce_kernel<<<(BATCH * OUTF / 4) / 256, 256>>>(out);
}

// round 14
// speedup vs baseline: 1.1422x; 1.1422x over previous
#include <cuda_runtime.h>
#include <cuda_bf16.h>
#include <cstdint>

// Problem constants
#define BATCH 64
#define OUTF  8192
#define INF   8192
#define RANK  16
#define GROUP 16
#define KC    64
#define NCHUNK (INF / KC)          // 128 total chunks
#define SPLITK 3
#define OUT_TILE 64
#define NOTILES (OUTF / OUT_TILE)  // 128
#define NBLOCKS (SPLITK * NOTILES) // 384

#define WS_STRIDE 68               // W_s row stride: conflict-free A reads + STS.128
#define XS_STRIDE 72               // x_s row stride: conflict-free LDS.128 B reads
#define WS_FLOATS (OUT_TILE * WS_STRIDE)   // 4352 floats per stage
#define XS_FLOATS (KC * XS_STRIDE)         // 4608 floats per stage
#define MAIN_SMEM ((2 * WS_FLOATS + 2 * XS_FLOATS) * 4)   // 71680 B dynamic

// scratch
__device__ float g_tp[4][BATCH * RANK];             // lora t partials (from prep)
__device__ __align__(16) float g_xt[INF * BATCH];   // [k][p] fragment-permuted tf32 x^T
__device__ __align__(16) float g_p[2 * BATCH * OUTF];  // partials for kq=1,2
__device__ int g_flag[NOTILES];

__device__ __forceinline__ unsigned tf32_rna(float x) {
    unsigned r;
    asm("cvt.rna.tf32.f32 %0, %1;" : "=r"(r) : "f"(x));
    return r;
}
__device__ __forceinline__ float tf32f(float x) {
    return __uint_as_float(tf32_rna(x));
}

// nvfp4 (e2m1) nibble -> fp32, times scale. n in [0,16).
__device__ __forceinline__ float dec4(unsigned n, float scr) {
    unsigned m = n & 7u;
    unsigned man = (m & ((m >> 1) | (m >> 2))) & 1u;
    unsigned bits = ((126u + (m >> 1)) << 23) | (man << 22);
    if (m == 0u) bits = 0u;
    bits |= (n & 8u) << 28;
    return __uint_as_float(bits) * scr;
}

__device__ __forceinline__ void mma_tf32_16x8x8(
    float& c0, float& c1, float& c2, float& c3,
    unsigned a0, unsigned a1, unsigned a2, unsigned a3,
    unsigned b0, unsigned b1)
{
    asm volatile(
        "mma.sync.aligned.m16n8k8.row.col.f32.tf32.tf32.f32 "
        "{%0,%1,%2,%3}, {%4,%5,%6,%7}, {%8,%9}, {%0,%1,%2,%3};"
        : "+f"(c0), "+f"(c1), "+f"(c2), "+f"(c3)
        : "r"(a0), "r"(a1), "r"(a2), "r"(a3), "r"(b0), "r"(b1));
}

__device__ __forceinline__ void cp16(uint32_t dst_smem, const void* src) {
    asm volatile("cp.async.cg.shared.global [%0], [%1], 16;"
                 :: "r"(dst_smem), "l"(src));
}
__device__ __forceinline__ void cp_commit() {
    asm volatile("cp.async.commit_group;" ::: "memory");
}
__device__ __forceinline__ void cp_wait0() {
    asm volatile("cp.async.wait_group 0;" ::: "memory");
}

// ---------------------------------------------------------------------------
// Prep kernel (512 threads):
//  block 0 additionally zeroes the split-K flags (graph replays re-run this).
//  blocks [0,256):    g_tp[kq][b][r] = partial lora t over one K quarter
//  blocks [256,384):  g_xt[k][p] = tf32(x[perm(p)][k]) for one 64-k slab,
//    permuted col p = 32h + 4g + j holds batch 32h + 8j + g
// ---------------------------------------------------------------------------
__global__ __launch_bounds__(512) void prep_kernel(
    const float* __restrict__ x, const float* __restrict__ A)
{
    __shared__ float ts[64][65];
    const int tid = threadIdx.x;

    if (blockIdx.x == 0 && tid < NOTILES) g_flag[tid] = 0;

    if (blockIdx.x < 256) {
        const int b  = blockIdx.x >> 2;
        const int kq = blockIdx.x & 3;
        const int r = tid & 15;
        const int part = tid >> 4;          // 0..31, 64 elems each

        const float* xr = x + (size_t)b * INF + kq * (INF / 4) + part * 64;
        const float* ar = A + (size_t)r * INF + kq * (INF / 4) + part * 64;

        float s0 = 0.f, s1 = 0.f, s2 = 0.f, s3 = 0.f;
        #pragma unroll
        for (int j = 0; j < 64; j += 16) {
            #pragma unroll
            for (int u = 0; u < 4; u++) {
                float4 xv = *reinterpret_cast<const float4*>(xr + j + 4 * u);
                float4 av = *reinterpret_cast<const float4*>(ar + j + 4 * u);
                float d = xv.x * av.x + xv.y * av.y + xv.z * av.z + xv.w * av.w;
                if (u == 0) s0 += d; else if (u == 1) s1 += d;
                else if (u == 2) s2 += d; else s3 += d;
            }
        }
        float* red = &ts[0][0];
        red[tid] = (s0 + s1) + (s2 + s3);
        __syncthreads();
        if (tid < 16) {
            float t = 0.0f;
            #pragma unroll
            for (int p = 0; p < 32; p++) t += red[p * 16 + tid];
            g_tp[kq][b * RANK + tid] = t;
        }
    } else {
        const int slab = blockIdx.x - 256;
        const int k0 = slab * 64;
        const int b = tid >> 3;             // 0..63
        const int q = tid & 7;              // 0..7 -> float4 cols 2q, 2q+1
        const float4* x4 = reinterpret_cast<const float4*>(x);

        #pragma unroll
        for (int p = 0; p < 2; p++) {
            const int fp = 2 * q + p;
            float4 v = x4[(size_t)b * (INF / 4) + (k0 >> 2) + fp];
            const int kk = fp * 4;
            ts[kk + 0][b] = v.x;
            ts[kk + 1][b] = v.y;
            ts[kk + 2][b] = v.z;
            ts[kk + 3][b] = v.w;
        }
        __syncthreads();

        float4* out4 = reinterpret_cast<float4*>(g_xt) + (size_t)slab * 1024;
        #pragma unroll
        for (int p = 0; p < 2; p++) {
            const int f = tid + 512 * p;
            const int k = f >> 4;
            const int col4 = f & 15;
            const int h = (col4 >> 3) * 32;
            const int g = col4 & 7;
            out4[f] = make_float4(tf32f(ts[k][h + 0 + g]),
                                  tf32f(ts[k][h + 8 + g]),
                                  tf32f(ts[k][h + 16 + g]),
                                  tf32f(ts[k][h + 24 + g]));
        }
    }
}

// ---------------------------------------------------------------------------
// Main kernel: split-K=3, OUT_TILE=64, 3 CTAs/SM, cp.async x staging,
// double-buffered W (ALU decode) and x, one sync per chunk, fused reduce.
//  grid = 384: blockIdx = otile | (kq << 7). 256 threads (8 warps).
//  kq=0 owns chunks [86,128) + lora + final combine; kq=1: [0,43); kq=2: [43,86).
// ---------------------------------------------------------------------------
__global__ __launch_bounds__(256, 3) void qlora_main_kernel(
    const int* __restrict__ pw,        // one packed BYTE per int32 element
    const float* __restrict__ sc,
    const float* __restrict__ lB,
    float* __restrict__ out)
{
    extern __shared__ float dsm[];
    float* Wbase = dsm;                        // 2 stages of WS_FLOATS
    float* Xbase = dsm + 2 * WS_FLOATS;        // 2 stages of XS_FLOATS

    const int tid   = threadIdx.x;
    const int lane  = tid & 31;
    const int warp  = tid >> 5;
    const int otile = blockIdx.x & (NOTILES - 1);
    const int kq    = blockIdx.x >> 7;
    const int o0    = otile * OUT_TILE;

    const int cbase = (kq == 0) ? 86 : ((kq == 1) ? 0 : 43);
    const int nch   = (kq == 0) ? 42 : 43;

    // ---- W staging roles (conflict-free STS.128 phases) ----
    const int wg   = (tid >> 3) & 3;
    const int wrow = (tid & 7) | ((tid >> 5) << 3);
    const int* pw_row = pw + (size_t)(o0 + wrow) * (INF / 2) + cbase * 32 + wg * 8;
    const float* sc_row = sc + (size_t)(o0 + wrow) * (INF / GROUP) + cbase * 4 + wg;
    float* wdst_base = Wbase + wrow * WS_STRIDE + wg * 16;

    // ---- x cp.async staging: 4 x 16B per thread per chunk ----
    const float4* xt4 = reinterpret_cast<const float4*>(g_xt) + (size_t)cbase * 1024;
    const uint32_t xs_u32 = (uint32_t)__cvta_generic_to_shared(Xbase);
    uint32_t xoff[4];
    #pragma unroll
    for (int p = 0; p < 4; p++) {
        const int f = tid + 256 * p;
        const int k = f >> 4;
        const int c4 = (f & 15) * 4;
        xoff[p] = (uint32_t)((k * XS_STRIDE + c4) * 4);
    }

    // warp tiling: m16 x n32
    const int m0  = (warp & 3) * 16;
    const int nb  = (warp >> 2) * 32;
    const int gid = lane >> 2;
    const int tig = lane & 3;
    const int boff = nb + 4 * gid;

    const int ra0 = (m0 + gid) * WS_STRIDE;
    const int ra1 = ra0 + 8 * WS_STRIDE;

    float acc[4][4];
    #pragma unroll
    for (int j = 0; j < 4; j++)
        #pragma unroll
        for (int e = 0; e < 4; e++) acc[j][e] = 0.0f;

    // ---- prologue: async-copy x chunk 0, decode W chunk 0, prefetch codes 1 ----
    #pragma unroll
    for (int p = 0; p < 4; p++)
        cp16(xs_u32 + xoff[p], xt4 + tid + 256 * p);
    cp_commit();

    uint4 pa = *reinterpret_cast<const uint4*>(pw_row);
    uint4 pb = *reinterpret_cast<const uint4*>(pw_row + 4);
    float scr = sc_row[0];
    {
        unsigned codes[8] = { pa.x, pa.y, pa.z, pa.w, pb.x, pb.y, pb.z, pb.w };
        float wv[16];
        #pragma unroll
        for (int j = 0; j < 8; j++) {
            const unsigned cb = codes[j] & 0xFFu;
            wv[2 * j]     = dec4(cb & 15u, scr);   // mma.tf32 truncates low bits
            wv[2 * j + 1] = dec4(cb >> 4, scr);
        }
        #pragma unroll
        for (int q = 0; q < 4; q++)
            *reinterpret_cast<float4*>(wdst_base + q * 4) =
                make_float4(wv[q * 4], wv[q * 4 + 1], wv[q * 4 + 2], wv[q * 4 + 3]);
    }
    pa = *reinterpret_cast<const uint4*>(pw_row + 32);
    pb = *reinterpret_cast<const uint4*>(pw_row + 36);
    scr = sc_row[4];
    cp_wait0();
    __syncthreads();

    for (int c = 0; c < nch; c++) {
        // ---- issue async x copy for chunk c+1 into the other stage ----
        if (c + 1 < nch) {
            const uint32_t xd = xs_u32 + ((c + 1) & 1) * (XS_FLOATS * 4);
            const float4* src = xt4 + (size_t)(c + 1) * 1024;
            #pragma unroll
            for (int p = 0; p < 4; p++)
                cp16(xd + xoff[p], src + tid + 256 * p);
            cp_commit();
        }

        // ---- MMA phase on stage c&1 ----
        const float* Wbuf = Wbase + (c & 1) * WS_FLOATS;
        const float* Xbuf = Xbase + (c & 1) * XS_FLOATS;
        #pragma unroll
        for (int s = 0; s < 8; s++) {
            const int k0i = s * 8 + tig;
            unsigned a0 = __float_as_uint(Wbuf[ra0 + k0i]);
            unsigned a1 = __float_as_uint(Wbuf[ra1 + k0i]);
            unsigned a2 = __float_as_uint(Wbuf[ra0 + k0i + 4]);
            unsigned a3 = __float_as_uint(Wbuf[ra1 + k0i + 4]);
            const float* bp = Xbuf + k0i * XS_STRIDE + boff;
            float4 b0v = *reinterpret_cast<const float4*>(bp);
            float4 b1v = *reinterpret_cast<const float4*>(bp + 4 * XS_STRIDE);
            mma_tf32_16x8x8(acc[0][0], acc[0][1], acc[0][2], acc[0][3],
                            a0, a1, a2, a3, __float_as_uint(b0v.x), __float_as_uint(b1v.x));
            mma_tf32_16x8x8(acc[1][0], acc[1][1], acc[1][2], acc[1][3],
                            a0, a1, a2, a3, __float_as_uint(b0v.y), __float_as_uint(b1v.y));
            mma_tf32_16x8x8(acc[2][0], acc[2][1], acc[2][2], acc[2][3],
                            a0, a1, a2, a3, __float_as_uint(b0v.z), __float_as_uint(b1v.z));
            mma_tf32_16x8x8(acc[3][0], acc[3][1], acc[3][2], acc[3][3],
                            a0, a1, a2, a3, __float_as_uint(b0v.w), __float_as_uint(b1v.w));
        }

        // ---- decode W chunk c+1 into the other stage (overlaps MMA drain) ----
        if (c + 1 < nch) {
            unsigned codes[8] = { pa.x, pa.y, pa.z, pa.w, pb.x, pb.y, pb.z, pb.w };
            float wv[16];
            #pragma unroll
            for (int j = 0; j < 8; j++) {
                const unsigned cb = codes[j] & 0xFFu;
                wv[2 * j]     = dec4(cb & 15u, scr);
                wv[2 * j + 1] = dec4(cb >> 4, scr);
            }
            float* wdst = wdst_base + ((c + 1) & 1) * WS_FLOATS;
            #pragma unroll
            for (int q = 0; q < 4; q++)
                *reinterpret_cast<float4*>(wdst + q * 4) =
                    make_float4(wv[q * 4], wv[q * 4 + 1], wv[q * 4 + 2], wv[q * 4 + 3]);

            if (c + 2 < nch) {
                const int* pn = pw_row + (c + 2) * 32;
                pa = *reinterpret_cast<const uint4*>(pn);
                pb = *reinterpret_cast<const uint4*>(pn + 4);
                scr = sc_row[(c + 2) * 4];
            }
        }
        cp_wait0();
        __syncthreads();
    }

    // ---- epilogue ----
    if (kq != 0) {
        float* pout = g_p + (size_t)(kq - 1) * BATCH * OUTF;
        #pragma unroll
        for (int j = 0; j < 4; j++) {
            const int bc0 = nb + 8 * j + 2 * tig;
            const int bc1 = bc0 + 1;
            const int og0 = o0 + m0 + gid;
            pout[(size_t)bc0 * OUTF + og0]     = acc[j][0];
            pout[(size_t)bc1 * OUTF + og0]     = acc[j][1];
            pout[(size_t)bc0 * OUTF + og0 + 8] = acc[j][2];
            pout[(size_t)bc1 * OUTF + og0 + 8] = acc[j][3];
        }
        __threadfence();
        __syncthreads();
        if (tid == 0) atomicAdd(&g_flag[otile], 1);
    } else {
        // lora term (overlaps the peers' tail)
        float* lb_s = dsm;                 // 1024 floats
        float* t_s  = dsm + 1024;          // 1024 floats
        for (int i = tid; i < OUT_TILE * RANK; i += 256) {
            lb_s[i] = lB[(size_t)o0 * RANK + i];
            t_s[i]  = (g_tp[0][i] + g_tp[1][i]) + (g_tp[2][i] + g_tp[3][i]);
        }
        __syncthreads();

        float lbr0[RANK], lbr1[RANK];
        #pragma unroll
        for (int r = 0; r < RANK; r++) {
            lbr0[r] = lb_s[(m0 + gid) * RANK + r];
            lbr1[r] = lb_s[(m0 + gid + 8) * RANK + r];
        }
        float d[4][4];
        #pragma unroll
        for (int j = 0; j < 4; j++) {
            const int bc0 = nb + 8 * j + 2 * tig;
            const int bc1 = bc0 + 1;
            float d00 = 0.f, d01 = 0.f, d10 = 0.f, d11 = 0.f;
            #pragma unroll
            for (int r = 0; r < RANK; r++) {
                const float t0 = t_s[bc0 * RANK + r];
                const float t1 = t_s[bc1 * RANK + r];
                d00 += t0 * lbr0[r];
                d01 += t1 * lbr0[r];
                d10 += t0 * lbr1[r];
                d11 += t1 * lbr1[r];
            }
            d[j][0] = d00; d[j][1] = d01; d[j][2] = d10; d[j][3] = d11;
        }

        // wait for both peer partials (all CTAs resident -> no deadlock)
        if (tid == 0) {
            while (atomicAdd(&g_flag[otile], 0) < 2) {}
        }
        __syncthreads();
        __threadfence();

        const float* p1 = g_p;
        const float* p2 = g_p + (size_t)BATCH * OUTF;
        #pragma unroll
        for (int j = 0; j < 4; j++) {
            const int bc0 = nb + 8 * j + 2 * tig;
            const int bc1 = bc0 + 1;
            const int og0 = o0 + m0 + gid;
            const size_t i00 = (size_t)bc0 * OUTF + og0;
            const size_t i01 = (size_t)bc1 * OUTF + og0;
            out[i00]     = acc[j][0] + d[j][0] + p1[i00]     + p2[i00];
            out[i01]     = acc[j][1] + d[j][1] + p1[i01]     + p2[i01];
            out[i00 + 8] = acc[j][2] + d[j][2] + p1[i00 + 8] + p2[i00 + 8];
            out[i01 + 8] = acc[j][3] + d[j][3] + p1[i01 + 8] + p2[i01 + 8];
        }
    }
}

// ---------------------------------------------------------------------------
// launch
// inputs: x f32(64,8192), packed_weight int32(8192,4096) [byte per element],
//   weight_block_scales f32(8192,512), lora_A f32(16,8192), lora_B f32(8192,16)
// output: f32 (64,8192)
// ---------------------------------------------------------------------------
extern "C" void kernel_launch(void* const* d_in, const int* in_sizes, int n_in,
                              void* d_out, int out_size)
{
    const float* x   = (const float*)d_in[0];
    const int*   pw  = (const int*)d_in[1];
    const float* sc  = (const float*)d_in[2];
    const float* lA  = (const float*)d_in[3];
    const float* lB  = (const float*)d_in[4];
    float*       out = (float*)d_out;

    cudaFuncSetAttribute(qlora_main_kernel,
                         cudaFuncAttributeMaxDynamicSharedMemorySize, MAIN_SMEM);

    prep_kernel<<<384, 512>>>(x, lA);
    qlora_main_kernel<<<NBLOCKS, 256, MAIN_SMEM>>>(pw, sc, lB, out);
}

// round 15
// speedup vs baseline: 1.6526x; 1.4469x over previous
#include <cuda_runtime.h>
#include <cuda_fp16.h>
#include <cuda_fp4.h>
#include <cstdint>

// Problem constants
#define BATCH 64
#define OUTF  8192
#define INF   8192
#define RANK  16
#define KC    64
#define SPLITK 4
#define NCHUNK_Q (INF / KC / SPLITK)   // 32 chunks per CTA
#define OUT_TILE 64
#define NOTILES (OUTF / OUT_TILE)      // 128
#define NBLOCKS (SPLITK * NOTILES)     // 512

#define W2_STRIDE 36                   // half2 units per W row (32 + pad4): A LDS conflict-free
#define X2_STRIDE 40                   // half2 units per x row (64/2*2... 32k2? no: 64 cols? see below)
// x_s: rows = 32 k2 (k-pairs), cols = 64 half2 (permuted batch) + pad 8 -> stride 40? cols=64!
// NOTE: row has 64 half2; stride must be 64+pad with pad making stride%32==8 -> 72.
#undef X2_STRIDE
#define X2_STRIDE 72
#define W2_WORDS (OUT_TILE * W2_STRIDE)    // 2304 words per stage
#define X2_WORDS (32 * X2_STRIDE)          // 2304 words per stage
#define MAIN_SMEM ((2 * W2_WORDS + 2 * X2_WORDS) * 4)   // 36864 B dynamic

// scratch
__device__ float g_tp[4][BATCH * RANK];                 // lora t partials
__device__ __align__(16) unsigned g_xt2[(INF / 2) * BATCH];  // [k2][p] half2(x[2k2],x[2k2+1]), 1MB
__device__ __align__(16) float g_p[SPLITK * BATCH * OUTF];   // split-K partials (8MB)
__device__ int g_flag[NOTILES];

__device__ __forceinline__ void mma_f16_16816(
    float& c0, float& c1, float& c2, float& c3,
    unsigned a0, unsigned a1, unsigned a2, unsigned a3,
    unsigned b0, unsigned b1)
{
    asm volatile(
        "mma.sync.aligned.m16n8k16.row.col.f32.f16.f16.f32 "
        "{%0,%1,%2,%3}, {%4,%5,%6,%7}, {%8,%9}, {%0,%1,%2,%3};"
        : "+f"(c0), "+f"(c1), "+f"(c2), "+f"(c3)
        : "r"(a0), "r"(a1), "r"(a2), "r"(a3), "r"(b0), "r"(b1));
}

__device__ __forceinline__ void cp16(uint32_t dst_smem, const void* src) {
    asm volatile("cp.async.cg.shared.global [%0], [%1], 16;"
                 :: "r"(dst_smem), "l"(src));
}
__device__ __forceinline__ void cp_commit() {
    asm volatile("cp.async.commit_group;" ::: "memory");
}
__device__ __forceinline__ void cp_wait0() {
    asm volatile("cp.async.wait_group 0;" ::: "memory");
}

// decode 8 code-ints (16 nvfp4 weights, one scale group) -> 8 half2 -> 2 STS.128
__device__ __forceinline__ void decode16(uint4 u0, uint4 u1, __half2 ss, unsigned* dst)
{
    unsigned codes[8] = { u0.x, u0.y, u0.z, u0.w, u1.x, u1.y, u1.z, u1.w };
    unsigned w[8];
    #pragma unroll
    for (int j = 0; j < 8; j++) {
        __half2_raw hr = __nv_cvt_fp4x2_to_halfraw2(
            (__nv_fp4x2_storage_t)(codes[j] & 0xFFu), __NV_E2M1);
        __half2 hv = *reinterpret_cast<__half2*>(&hr);   // .x = low nibble = even k
        __half2 wv = __hmul2(hv, ss);
        w[j] = *reinterpret_cast<unsigned*>(&wv);
    }
    *reinterpret_cast<uint4*>(dst)     = make_uint4(w[0], w[1], w[2], w[3]);
    *reinterpret_cast<uint4*>(dst + 4) = make_uint4(w[4], w[5], w[6], w[7]);
}

// ---------------------------------------------------------------------------
// Prep kernel (512 threads):
//  block 0 zeroes the split-K flags (graph replays re-run this)
//  blocks [0,256):    g_tp[kq][b][r] = partial lora t over one K quarter (fp32)
//  blocks [256,384):  g_xt2[k2][p] = half2(x[perm(p)][2k2], x[perm(p)][2k2+1]),
//    permuted col p = 32h + 4g + j holds batch 32h + 8j + g
// ---------------------------------------------------------------------------
__global__ __launch_bounds__(512) void prep_kernel(
    const float* __restrict__ x, const float* __restrict__ A)
{
    __shared__ float ts[64][65];
    const int tid = threadIdx.x;

    if (blockIdx.x == 0 && tid < NOTILES) g_flag[tid] = 0;

    if (blockIdx.x < 256) {
        const int b  = blockIdx.x >> 2;
        const int kq = blockIdx.x & 3;
        const int r = tid & 15;
        const int part = tid >> 4;          // 0..31, 64 elems each

        const float* xr = x + (size_t)b * INF + kq * (INF / 4) + part * 64;
        const float* ar = A + (size_t)r * INF + kq * (INF / 4) + part * 64;

        float s0 = 0.f, s1 = 0.f, s2 = 0.f, s3 = 0.f;
        #pragma unroll
        for (int j = 0; j < 64; j += 16) {
            #pragma unroll
            for (int u = 0; u < 4; u++) {
                float4 xv = *reinterpret_cast<const float4*>(xr + j + 4 * u);
                float4 av = *reinterpret_cast<const float4*>(ar + j + 4 * u);
                float d = xv.x * av.x + xv.y * av.y + xv.z * av.z + xv.w * av.w;
                if (u == 0) s0 += d; else if (u == 1) s1 += d;
                else if (u == 2) s2 += d; else s3 += d;
            }
        }
        float* red = &ts[0][0];
        red[tid] = (s0 + s1) + (s2 + s3);
        __syncthreads();
        if (tid < 16) {
            float t = 0.0f;
            #pragma unroll
            for (int p = 0; p < 32; p++) t += red[p * 16 + tid];
            g_tp[kq][b * RANK + tid] = t;
        }
    } else {
        const int slab = blockIdx.x - 256;       // 0..127, 64 k each (32 k2)
        const int k0 = slab * 64;
        const int b = tid >> 3;                  // 0..63
        const int q = tid & 7;
        const float4* x4 = reinterpret_cast<const float4*>(x);

        #pragma unroll
        for (int p = 0; p < 2; p++) {
            const int fp = 2 * q + p;
            float4 v = x4[(size_t)b * (INF / 4) + (k0 >> 2) + fp];
            const int kk = fp * 4;
            ts[kk + 0][b] = v.x;
            ts[kk + 1][b] = v.y;
            ts[kk + 2][b] = v.z;
            ts[kk + 3][b] = v.w;
        }
        __syncthreads();

        // 512 threads, one uint4 each: (k2 local, col4) -> 4 batches x half2
        const int k2l  = tid >> 4;               // 0..31
        const int col4 = tid & 15;
        const int h = (col4 >> 3) * 32;
        const int g = col4 & 7;
        unsigned wv[4];
        #pragma unroll
        for (int j = 0; j < 4; j++) {
            const int b_j = h + 8 * j + g;
            __half2 h2 = __floats2half2_rn(ts[2 * k2l][b_j], ts[2 * k2l + 1][b_j]);
            wv[j] = *reinterpret_cast<unsigned*>(&h2);
        }
        uint4* out4 = reinterpret_cast<uint4*>(g_xt2) + (size_t)slab * 512;
        out4[k2l * 16 + col4] = make_uint4(wv[0], wv[1], wv[2], wv[3]);
    }
}

// ---------------------------------------------------------------------------
// Main kernel: split-K=4, f16 datapath, double-buffered W/x, one sync/chunk,
// last-finisher combine (no spin).
//  grid = 512: blockIdx = otile | (kq << 7). 256 threads (8 warps: 4m x 2n).
// ---------------------------------------------------------------------------
__global__ __launch_bounds__(256, 3) void qlora_main_kernel(
    const int* __restrict__ pw,        // one packed BYTE per int32 element
    const float* __restrict__ sc,
    const float* __restrict__ lB,
    float* __restrict__ out)
{
    extern __shared__ unsigned dsm[];
    unsigned* Wbase = dsm;                      // 2 stages of W2_WORDS
    unsigned* Xbase = dsm + 2 * W2_WORDS;       // 2 stages of X2_WORDS
    __shared__ int s_last;

    const int tid   = threadIdx.x;
    const int lane  = tid & 31;
    const int warp  = tid >> 5;
    const int otile = blockIdx.x & (NOTILES - 1);
    const int kq    = blockIdx.x >> 7;
    const int o0    = otile * OUT_TILE;

    // ---- W staging roles ----
    const int wg   = (tid >> 3) & 3;            // scale group within chunk
    const int wrow = (tid & 7) | ((tid >> 5) << 3);
    const int* pw_row = pw + (size_t)(o0 + wrow) * (INF / 2) + kq * (NCHUNK_Q * 32) + wg * 8;
    const float* sc_row = sc + (size_t)(o0 + wrow) * (INF / 16) + kq * (NCHUNK_Q * 4) + wg;
    unsigned* wdst_base = Wbase + wrow * W2_STRIDE + wg * 8;

    // ---- x cp.async staging: 2 x 16B per thread per chunk ----
    const uint4* xt4 = reinterpret_cast<const uint4*>(g_xt2) + (size_t)kq * NCHUNK_Q * 512;
    const uint32_t xs_u32 = (uint32_t)__cvta_generic_to_shared(Xbase);
    uint32_t xoff[2];
    #pragma unroll
    for (int p = 0; p < 2; p++) {
        const int f = tid + 256 * p;
        xoff[p] = (uint32_t)((((f >> 4) * X2_STRIDE) + (f & 15) * 4) * 4);
    }

    // warp tiling: m16 x n32
    const int m0  = (warp & 3) * 16;
    const int nb  = (warp >> 2) * 32;
    const int gid = lane >> 2;
    const int tig = lane & 3;
    const int boff = nb + 4 * gid;

    const int ra0 = (m0 + gid) * W2_STRIDE;
    const int ra1 = ra0 + 8 * W2_STRIDE;

    float acc[4][4];
    #pragma unroll
    for (int j = 0; j < 4; j++)
        #pragma unroll
        for (int e = 0; e < 4; e++) acc[j][e] = 0.0f;

    // ---- prologue: stage chunk 0; prefetch chunk 1 codes ----
    #pragma unroll
    for (int p = 0; p < 2; p++)
        cp16(xs_u32 + xoff[p], xt4 + tid + 256 * p);
    cp_commit();

    uint4 pa = *reinterpret_cast<const uint4*>(pw_row);
    uint4 pb = *reinterpret_cast<const uint4*>(pw_row + 4);
    float scr = sc_row[0];
    decode16(pa, pb, __float2half2_rn(scr), wdst_base);

    pa = *reinterpret_cast<const uint4*>(pw_row + 32);
    pb = *reinterpret_cast<const uint4*>(pw_row + 36);
    scr = sc_row[4];
    cp_wait0();
    __syncthreads();

    for (int c = 0; c < NCHUNK_Q; c++) {
        // ---- async x copy for chunk c+1 ----
        if (c + 1 < NCHUNK_Q) {
            const uint32_t xd = xs_u32 + ((c + 1) & 1) * (X2_WORDS * 4);
            const uint4* src = xt4 + (size_t)(c + 1) * 512;
            #pragma unroll
            for (int p = 0; p < 2; p++)
                cp16(xd + xoff[p], src + tid + 256 * p);
            cp_commit();
        }

        // ---- MMA phase on stage c&1: 4 k16-groups ----
        const unsigned* Wbuf = Wbase + (c & 1) * W2_WORDS;
        const unsigned* Xbuf = Xbase + (c & 1) * X2_WORDS;
        #pragma unroll
        for (int s = 0; s < 4; s++) {
            const int k2 = s * 8 + tig;
            unsigned a0 = Wbuf[ra0 + k2];
            unsigned a1 = Wbuf[ra1 + k2];
            unsigned a2 = Wbuf[ra0 + k2 + 4];
            unsigned a3 = Wbuf[ra1 + k2 + 4];
            const unsigned* bp = Xbuf + k2 * X2_STRIDE + boff;
            uint4 b0v = *reinterpret_cast<const uint4*>(bp);
            uint4 b1v = *reinterpret_cast<const uint4*>(bp + 4 * X2_STRIDE);
            mma_f16_16816(acc[0][0], acc[0][1], acc[0][2], acc[0][3],
                          a0, a1, a2, a3, b0v.x, b1v.x);
            mma_f16_16816(acc[1][0], acc[1][1], acc[1][2], acc[1][3],
                          a0, a1, a2, a3, b0v.y, b1v.y);
            mma_f16_16816(acc[2][0], acc[2][1], acc[2][2], acc[2][3],
                          a0, a1, a2, a3, b0v.z, b1v.z);
            mma_f16_16816(acc[3][0], acc[3][1], acc[3][2], acc[3][3],
                          a0, a1, a2, a3, b0v.w, b1v.w);
        }

        // ---- decode W chunk c+1 (overlaps MMA drain) ----
        if (c + 1 < NCHUNK_Q) {
            decode16(pa, pb, __float2half2_rn(scr),
                     wdst_base + ((c + 1) & 1) * W2_WORDS);
            if (c + 2 < NCHUNK_Q) {
                const int* pn = pw_row + (c + 2) * 32;
                pa = *reinterpret_cast<const uint4*>(pn);
                pb = *reinterpret_cast<const uint4*>(pn + 4);
                scr = sc_row[(c + 2) * 4];
            }
        }
        cp_wait0();
        __syncthreads();
    }

    // ---- write partial ----
    float* pout = g_p + (size_t)kq * BATCH * OUTF;
    #pragma unroll
    for (int j = 0; j < 4; j++) {
        const int bc0 = nb + 8 * j + 2 * tig;
        const int bc1 = bc0 + 1;
        const int og0 = o0 + m0 + gid;
        pout[(size_t)bc0 * OUTF + og0]     = acc[j][0];
        pout[(size_t)bc1 * OUTF + og0]     = acc[j][1];
        pout[(size_t)bc0 * OUTF + og0 + 8] = acc[j][2];
        pout[(size_t)bc1 * OUTF + og0 + 8] = acc[j][3];
    }
    __threadfence();
    __syncthreads();
    if (tid == 0) s_last = atomicAdd(&g_flag[otile], 1);
    __syncthreads();

    // ---- last finisher combines all 4 partials + lora -> out ----
    if (s_last == SPLITK - 1) {
        __threadfence();
        float* lb_s = reinterpret_cast<float*>(dsm);         // 1024
        float* t_s  = lb_s + OUT_TILE * RANK;                // 1024
        for (int i = tid; i < OUT_TILE * RANK; i += 256) {
            lb_s[i] = lB[(size_t)o0 * RANK + i];
            t_s[i]  = (g_tp[0][i] + g_tp[1][i]) + (g_tp[2][i] + g_tp[3][i]);
        }
        __syncthreads();

        const int b  = tid >> 2;        // batch row
        const int q  = tid & 3;
        float tb[RANK];
        #pragma unroll
        for (int r = 0; r < RANK; r++) tb[r] = t_s[b * RANK + r];

        const float4* P = reinterpret_cast<const float4*>(g_p);
        const size_t qstride = (size_t)(BATCH * OUTF) / 4;
        float4* O = reinterpret_cast<float4*>(out);

        #pragma unroll
        for (int p = 0; p < 4; p++) {
            const int c4 = q + 4 * p;                       // float4 col chunk 0..15
            const size_t gi = (size_t)b * (OUTF / 4) + (o0 >> 2) + c4;
            float4 s0 = P[gi];
            float4 s1 = P[gi + qstride];
            float4 s2 = P[gi + 2 * qstride];
            float4 s3 = P[gi + 3 * qstride];
            float4 r = make_float4((s0.x + s1.x) + (s2.x + s3.x),
                                   (s0.y + s1.y) + (s2.y + s3.y),
                                   (s0.z + s1.z) + (s2.z + s3.z),
                                   (s0.w + s1.w) + (s2.w + s3.w));
            float dv[4] = {0.f, 0.f, 0.f, 0.f};
            #pragma unroll
            for (int e = 0; e < 4; e++) {
                const float* lbr = &lb_s[(c4 * 4 + e) * RANK];
                float d = 0.f;
                #pragma unroll
                for (int rr = 0; rr < RANK; rr++) d += tb[rr] * lbr[rr];
                dv[e] = d;
            }
            r.x += dv[0]; r.y += dv[1]; r.z += dv[2]; r.w += dv[3];
            O[gi] = r;
        }
    }
}

// ---------------------------------------------------------------------------
// launch
// inputs: x f32(64,8192), packed_weight int32(8192,4096) [byte per element],
//   weight_block_scales f32(8192,512), lora_A f32(16,8192), lora_B f32(8192,16)
// output: f32 (64,8192)
// ---------------------------------------------------------------------------
extern "C" void kernel_launch(void* const* d_in, const int* in_sizes, int n_in,
                              void* d_out, int out_size)
{
    const float* x   = (const float*)d_in[0];
    const int*   pw  = (const int*)d_in[1];
    const float* sc  = (const float*)d_in[2];
    const float* lA  = (const float*)d_in[3];
    const float* lB  = (const float*)d_in[4];
    float*       out = (float*)d_out;

    cudaFuncSetAttribute(qlora_main_kernel,
                         cudaFuncAttributeMaxDynamicSharedMemorySize, MAIN_SMEM);

    prep_kernel<<<384, 512>>>(x, lA);
    qlora_main_kernel<<<NBLOCKS, 256, MAIN_SMEM>>>(pw, sc, lB, out);
}

// round 17
// speedup vs baseline: 1.6575x; 1.0029x over previous
#include <cuda_runtime.h>
#include <cuda_fp16.h>
#include <cuda_fp4.h>
#include <cstdint>

// Problem constants
#define BATCH 64
#define OUTF  8192
#define INF   8192
#define RANK  16
#define KC    64
#define NCHUNK 128                     // total K chunks
#define SPLITK 3
#define OUT_TILE 64
#define NOTILES (OUTF / OUT_TILE)      // 128
#define NBLOCKS (SPLITK * NOTILES)     // 384 = one full wave at 3 CTAs/SM

#define W2_STRIDE 36                   // half2 units per W row (32 + pad 4)
#define X2_STRIDE 72                   // half2 units per x k2-row (64 + pad 8)
#define W2_WORDS (OUT_TILE * W2_STRIDE)    // 2304 words per stage
#define X2_WORDS (32 * X2_STRIDE)          // 2304 words per stage
#define MAIN_SMEM ((2 * W2_WORDS + 2 * X2_WORDS) * 4)   // 36864 B dynamic

// scratch
__device__ float g_tp[4][BATCH * RANK];                      // lora t partials
__device__ __align__(16) unsigned g_xt2[(INF / 2) * BATCH];  // [k2][p] half2 x^T (1MB)
__device__ __align__(16) float g_p[SPLITK * BATCH * OUTF];   // split-K partials (6MB)
__device__ int g_flag[NOTILES];

__device__ __forceinline__ void mma_f16_16816(
    float& c0, float& c1, float& c2, float& c3,
    unsigned a0, unsigned a1, unsigned a2, unsigned a3,
    unsigned b0, unsigned b1)
{
    asm volatile(
        "mma.sync.aligned.m16n8k16.row.col.f32.f16.f16.f32 "
        "{%0,%1,%2,%3}, {%4,%5,%6,%7}, {%8,%9}, {%0,%1,%2,%3};"
        : "+f"(c0), "+f"(c1), "+f"(c2), "+f"(c3)
        : "r"(a0), "r"(a1), "r"(a2), "r"(a3), "r"(b0), "r"(b1));
}

__device__ __forceinline__ void cp16(uint32_t dst_smem, const void* src) {
    asm volatile("cp.async.cg.shared.global [%0], [%1], 16;"
                 :: "r"(dst_smem), "l"(src));
}
__device__ __forceinline__ void cp_commit() {
    asm volatile("cp.async.commit_group;" ::: "memory");
}
__device__ __forceinline__ void cp_wait0() {
    asm volatile("cp.async.wait_group 0;" ::: "memory");
}

// decode 8 code-ints (16 nvfp4 weights, one scale group) -> 8 half2 -> 2 STS.128
__device__ __forceinline__ void decode16(uint4 u0, uint4 u1, __half2 ss, unsigned* dst)
{
    unsigned codes[8] = { u0.x, u0.y, u0.z, u0.w, u1.x, u1.y, u1.z, u1.w };
    unsigned w[8];
    #pragma unroll
    for (int j = 0; j < 8; j++) {
        __half2_raw hr = __nv_cvt_fp4x2_to_halfraw2(
            (__nv_fp4x2_storage_t)(codes[j] & 0xFFu), __NV_E2M1);
        __half2 hv = *reinterpret_cast<__half2*>(&hr);   // .x = low nibble = even k
        __half2 wv = __hmul2(hv, ss);
        w[j] = *reinterpret_cast<unsigned*>(&wv);
    }
    *reinterpret_cast<uint4*>(dst)     = make_uint4(w[0], w[1], w[2], w[3]);
    *reinterpret_cast<uint4*>(dst + 4) = make_uint4(w[4], w[5], w[6], w[7]);
}

// ---------------------------------------------------------------------------
// Prep kernel (512 threads):
//  block 0 zeroes the split-K flags (graph replays re-run this)
//  blocks [0,256):    g_tp[kq][b][r] = partial lora t over one K quarter (fp32)
//  blocks [256,384):  g_xt2[k2][p] = half2(x[perm(p)][2k2], x[perm(p)][2k2+1]),
//    permuted col p = 32h + 4g + j holds batch 32h + 8j + g
// ---------------------------------------------------------------------------
__global__ __launch_bounds__(512) void prep_kernel(
    const float* __restrict__ x, const float* __restrict__ A)
{
    __shared__ float ts[64][65];
    const int tid = threadIdx.x;

    if (blockIdx.x == 0 && tid < NOTILES) g_flag[tid] = 0;

    if (blockIdx.x < 256) {
        const int b  = blockIdx.x >> 2;
        const int kq = blockIdx.x & 3;
        const int r = tid & 15;
        const int part = tid >> 4;          // 0..31, 64 elems each

        const float* xr = x + (size_t)b * INF + kq * (INF / 4) + part * 64;
        const float* ar = A + (size_t)r * INF + kq * (INF / 4) + part * 64;

        float s0 = 0.f, s1 = 0.f, s2 = 0.f, s3 = 0.f;
        #pragma unroll
        for (int j = 0; j < 64; j += 16) {
            #pragma unroll
            for (int u = 0; u < 4; u++) {
                float4 xv = *reinterpret_cast<const float4*>(xr + j + 4 * u);
                float4 av = *reinterpret_cast<const float4*>(ar + j + 4 * u);
                float d = xv.x * av.x + xv.y * av.y + xv.z * av.z + xv.w * av.w;
                if (u == 0) s0 += d; else if (u == 1) s1 += d;
                else if (u == 2) s2 += d; else s3 += d;
            }
        }
        float* red = &ts[0][0];
        red[tid] = (s0 + s1) + (s2 + s3);
        __syncthreads();
        if (tid < 16) {
            float t = 0.0f;
            #pragma unroll
            for (int p = 0; p < 32; p++) t += red[p * 16 + tid];
            g_tp[kq][b * RANK + tid] = t;
        }
    } else {
        const int slab = blockIdx.x - 256;       // 0..127, 64 k each (32 k2)
        const int k0 = slab * 64;
        const int b = tid >> 3;                  // 0..63
        const int q = tid & 7;
        const float4* x4 = reinterpret_cast<const float4*>(x);

        #pragma unroll
        for (int p = 0; p < 2; p++) {
            const int fp = 2 * q + p;
            float4 v = x4[(size_t)b * (INF / 4) + (k0 >> 2) + fp];
            const int kk = fp * 4;
            ts[kk + 0][b] = v.x;
            ts[kk + 1][b] = v.y;
            ts[kk + 2][b] = v.z;
            ts[kk + 3][b] = v.w;
        }
        __syncthreads();

        // 512 threads, one uint4 each: (k2 local, col4) -> 4 batches x half2
        const int k2l  = tid >> 4;               // 0..31
        const int col4 = tid & 15;
        const int h = (col4 >> 3) * 32;
        const int g = col4 & 7;
        unsigned wv[4];
        #pragma unroll
        for (int j = 0; j < 4; j++) {
            const int b_j = h + 8 * j + g;
            __half2 h2 = __floats2half2_rn(ts[2 * k2l][b_j], ts[2 * k2l + 1][b_j]);
            wv[j] = *reinterpret_cast<unsigned*>(&h2);
        }
        uint4* out4 = reinterpret_cast<uint4*>(g_xt2) + (size_t)slab * 512;
        out4[k2l * 16 + col4] = make_uint4(wv[0], wv[1], wv[2], wv[3]);
    }
}

// ---------------------------------------------------------------------------
// Main kernel: split-K=3 (single wave), f16 datapath, double-buffered W/x,
// one sync/chunk, ticket-based last-finisher combine.
//  grid = 384: blockIdx = otile | (kq << 7). 256 threads (8 warps: 4m x 2n).
//  kq=0: chunks [0,43); kq=1: [43,86); kq=2: [86,128).
// ---------------------------------------------------------------------------
__global__ __launch_bounds__(256, 3) void qlora_main_kernel(
    const int* __restrict__ pw,        // one packed BYTE per int32 element
    const float* __restrict__ sc,
    const float* __restrict__ lB,
    float* __restrict__ out)
{
    extern __shared__ unsigned dsm[];
    unsigned* Wbase = dsm;                      // 2 stages of W2_WORDS
    unsigned* Xbase = dsm + 2 * W2_WORDS;       // 2 stages of X2_WORDS
    __shared__ int s_last;

    const int tid   = threadIdx.x;
    const int lane  = tid & 31;
    const int warp  = tid >> 5;
    const int otile = blockIdx.x & (NOTILES - 1);
    const int kq    = blockIdx.x >> 7;
    const int o0    = otile * OUT_TILE;

    const int cbase = (kq == 0) ? 0 : ((kq == 1) ? 43 : 86);
    const int nch   = (kq == 2) ? 42 : 43;

    // ---- W staging roles ----
    const int wg   = (tid >> 3) & 3;            // scale group within chunk
    const int wrow = (tid & 7) | ((tid >> 5) << 3);
    const int* pw_row = pw + (size_t)(o0 + wrow) * (INF / 2) + cbase * 32 + wg * 8;
    const float* sc_row = sc + (size_t)(o0 + wrow) * (INF / 16) + cbase * 4 + wg;
    unsigned* wdst_base = Wbase + wrow * W2_STRIDE + wg * 8;

    // ---- x cp.async staging: 2 x 16B per thread per chunk ----
    const uint4* xt4 = reinterpret_cast<const uint4*>(g_xt2) + (size_t)cbase * 512;
    const uint32_t xs_u32 = (uint32_t)__cvta_generic_to_shared(Xbase);
    uint32_t xoff[2];
    #pragma unroll
    for (int p = 0; p < 2; p++) {
        const int f = tid + 256 * p;
        xoff[p] = (uint32_t)((((f >> 4) * X2_STRIDE) + (f & 15) * 4) * 4);
    }

    // warp tiling: m16 x n32
    const int m0  = (warp & 3) * 16;
    const int nb  = (warp >> 2) * 32;
    const int gid = lane >> 2;
    const int tig = lane & 3;
    const int boff = nb + 4 * gid;

    const int ra0 = (m0 + gid) * W2_STRIDE;
    const int ra1 = ra0 + 8 * W2_STRIDE;

    float acc[4][4];
    #pragma unroll
    for (int j = 0; j < 4; j++)
        #pragma unroll
        for (int e = 0; e < 4; e++) acc[j][e] = 0.0f;

    // ---- prologue: stage chunk 0; prefetch chunk 1 codes ----
    #pragma unroll
    for (int p = 0; p < 2; p++)
        cp16(xs_u32 + xoff[p], xt4 + tid + 256 * p);
    cp_commit();

    uint4 pa = *reinterpret_cast<const uint4*>(pw_row);
    uint4 pb = *reinterpret_cast<const uint4*>(pw_row + 4);
    float scr = sc_row[0];
    decode16(pa, pb, __float2half2_rn(scr), wdst_base);

    pa = *reinterpret_cast<const uint4*>(pw_row + 32);
    pb = *reinterpret_cast<const uint4*>(pw_row + 36);
    scr = sc_row[4];
    cp_wait0();
    __syncthreads();

    for (int c = 0; c < nch; c++) {
        // ---- async x copy for chunk c+1 ----
        if (c + 1 < nch) {
            const uint32_t xd = xs_u32 + ((c + 1) & 1) * (X2_WORDS * 4);
            const uint4* src = xt4 + (size_t)(c + 1) * 512;
            #pragma unroll
            for (int p = 0; p < 2; p++)
                cp16(xd + xoff[p], src + tid + 256 * p);
            cp_commit();
        }

        // ---- MMA phase on stage c&1: 4 k16-groups ----
        const unsigned* Wbuf = Wbase + (c & 1) * W2_WORDS;
        const unsigned* Xbuf = Xbase + (c & 1) * X2_WORDS;
        #pragma unroll
        for (int s = 0; s < 4; s++) {
            const int k2 = s * 8 + tig;
            unsigned a0 = Wbuf[ra0 + k2];
            unsigned a1 = Wbuf[ra1 + k2];
            unsigned a2 = Wbuf[ra0 + k2 + 4];
            unsigned a3 = Wbuf[ra1 + k2 + 4];
            const unsigned* bp = Xbuf + k2 * X2_STRIDE + boff;
            uint4 b0v = *reinterpret_cast<const uint4*>(bp);
            uint4 b1v = *reinterpret_cast<const uint4*>(bp + 4 * X2_STRIDE);
            mma_f16_16816(acc[0][0], acc[0][1], acc[0][2], acc[0][3],
                          a0, a1, a2, a3, b0v.x, b1v.x);
            mma_f16_16816(acc[1][0], acc[1][1], acc[1][2], acc[1][3],
                          a0, a1, a2, a3, b0v.y, b1v.y);
            mma_f16_16816(acc[2][0], acc[2][1], acc[2][2], acc[2][3],
                          a0, a1, a2, a3, b0v.z, b1v.z);
            mma_f16_16816(acc[3][0], acc[3][1], acc[3][2], acc[3][3],
                          a0, a1, a2, a3, b0v.w, b1v.w);
        }

        // ---- decode W chunk c+1 (overlaps MMA drain) ----
        if (c + 1 < nch) {
            decode16(pa, pb, __float2half2_rn(scr),
                     wdst_base + ((c + 1) & 1) * W2_WORDS);
            if (c + 2 < nch) {
                const int* pn = pw_row + (c + 2) * 32;
                pa = *reinterpret_cast<const uint4*>(pn);
                pb = *reinterpret_cast<const uint4*>(pn + 4);
                scr = sc_row[(c + 2) * 4];
            }
        }
        cp_wait0();
        __syncthreads();
    }

    // ---- write partial ----
    float* pout = g_p + (size_t)kq * BATCH * OUTF;
    #pragma unroll
    for (int j = 0; j < 4; j++) {
        const int bc0 = nb + 8 * j + 2 * tig;
        const int bc1 = bc0 + 1;
        const int og0 = o0 + m0 + gid;
        pout[(size_t)bc0 * OUTF + og0]     = acc[j][0];
        pout[(size_t)bc1 * OUTF + og0]     = acc[j][1];
        pout[(size_t)bc0 * OUTF + og0 + 8] = acc[j][2];
        pout[(size_t)bc1 * OUTF + og0 + 8] = acc[j][3];
    }
    __threadfence();
    __syncthreads();
    if (tid == 0) s_last = atomicAdd(&g_flag[otile], 1);
    __syncthreads();

    // ---- last finisher combines all partials + lora -> out ----
    if (s_last == SPLITK - 1) {
        __threadfence();
        float* lb_s = reinterpret_cast<float*>(dsm);         // 1024
        float* t_s  = lb_s + OUT_TILE * RANK;                // 1024
        for (int i = tid; i < OUT_TILE * RANK; i += 256) {
            lb_s[i] = lB[(size_t)o0 * RANK + i];
            t_s[i]  = (g_tp[0][i] + g_tp[1][i]) + (g_tp[2][i] + g_tp[3][i]);
        }
        __syncthreads();

        const int b  = tid >> 2;        // batch row
        const int q  = tid & 3;
        float tb[RANK];
        #pragma unroll
        for (int r = 0; r < RANK; r++) tb[r] = t_s[b * RANK + r];

        const float4* P = reinterpret_cast<const float4*>(g_p);
        const size_t qstride = (size_t)(BATCH * OUTF) / 4;
        float4* O = reinterpret_cast<float4*>(out);

        #pragma unroll
        for (int p = 0; p < 4; p++) {
            const int c4 = q + 4 * p;                       // float4 col chunk 0..15
            const size_t gi = (size_t)b * (OUTF / 4) + (o0 >> 2) + c4;
            float4 s0 = P[gi];
            float4 s1 = P[gi + qstride];
            float4 s2 = P[gi + 2 * qstride];
            float4 r = make_float4(s0.x + s1.x + s2.x,
                                   s0.y + s1.y + s2.y,
                                   s0.z + s1.z + s2.z,
                                   s0.w + s1.w + s2.w);
            float dv[4] = {0.f, 0.f, 0.f, 0.f};
            #pragma unroll
            for (int e = 0; e < 4; e++) {
                const float* lbr = &lb_s[(c4 * 4 + e) * RANK];
                float d = 0.f;
                #pragma unroll
                for (int rr = 0; rr < RANK; rr++) d += tb[rr] * lbr[rr];
                dv[e] = d;
            }
            r.x += dv[0]; r.y += dv[1]; r.z += dv[2]; r.w += dv[3];
            O[gi] = r;
        }
    }
}

// ---------------------------------------------------------------------------
// launch
// inputs: x f32(64,8192), packed_weight int32(8192,4096) [byte per element],
//   weight_block_scales f32(8192,512), lora_A f32(16,8192), lora_B f32(8192,16)
// output: f32 (64,8192)
// ---------------------------------------------------------------------------
extern "C" void kernel_launch(void* const* d_in, const int* in_sizes, int n_in,
                              void* d_out, int out_size)
{
    const float* x   = (const float*)d_in[0];
    const int*   pw  = (const int*)d_in[1];
    const float* sc  = (const float*)d_in[2];
    const float* lA  = (const float*)d_in[3];
    const float* lB  = (const float*)d_in[4];
    float*       out = (float*)d_out;

    cudaFuncSetAttribute(qlora_main_kernel,
                         cudaFuncAttributeMaxDynamicSharedMemorySize, MAIN_SMEM);

    prep_kernel<<<384, 512>>>(x, lA);
    qlora_main_kernel<<<NBLOCKS, 256, MAIN_SMEM>>>(pw, sc, lB, out);
}